// round 1
// baseline (speedup 1.0000x reference)
#include <cuda_runtime.h>
#include <math.h>

// Problem constants
#define B_    2
#define L_    13294
#define S_    13294
#define D_    256
#define NH_   8
#define HD_   32
#define M_    (B_ * L_)          // 26588 rows for all GEMMs

// Scratch (static device arrays — no allocation allowed)
__device__ float g_val  [(size_t)M_ * 256];  // value @ W_val   [B,S,NH,HD]
__device__ float g_off  [(size_t)M_ * 256];  // query @ W_off   [B,L,256]
__device__ float g_logit[(size_t)M_ * 128];  // query @ W_attn  [B,L,128]
__device__ float g_acc  [(size_t)M_ * 256];  // sampled output  [B,L,NH,HD]

// ---------------------------------------------------------------------------
// SGEMM with bias: C[M,N] = A[M,K] @ W[K,N] + b[N]
// 64x64 tile, BK=16, 256 threads, 4x4 microtile per thread. K,N multiples of
// 16/64; M guarded.
// ---------------------------------------------------------------------------
__global__ __launch_bounds__(256)
void sgemm_bias(const float* __restrict__ A, const float* __restrict__ W,
                const float* __restrict__ bias, float* __restrict__ C,
                int M, int N, int K) {
    __shared__ float As[16][64];
    __shared__ float Ws[16][64];

    const int t  = threadIdx.x;
    const int tx = t & 15;          // 0..15  -> N direction
    const int ty = t >> 4;          // 0..15  -> M direction
    const int m0 = blockIdx.y * 64;
    const int n0 = blockIdx.x * 64;

    // A-tile load mapping: each thread loads one float4 along K
    const int arow = t >> 2;        // 0..63
    const int akg  = (t & 3) * 4;   // 0,4,8,12
    // W-tile load mapping
    const int wrow = ty;            // 0..15
    const int wcol = tx * 4;        // 0..60

    float acc[4][4];
#pragma unroll
    for (int i = 0; i < 4; i++)
#pragma unroll
        for (int j = 0; j < 4; j++) acc[i][j] = 0.f;

    for (int k0 = 0; k0 < K; k0 += 16) {
        float4 a4 = make_float4(0.f, 0.f, 0.f, 0.f);
        if (m0 + arow < M)
            a4 = *(const float4*)&A[(size_t)(m0 + arow) * K + k0 + akg];
        As[akg + 0][arow] = a4.x;
        As[akg + 1][arow] = a4.y;
        As[akg + 2][arow] = a4.z;
        As[akg + 3][arow] = a4.w;

        float4 w4 = *(const float4*)&W[(size_t)(k0 + wrow) * N + n0 + wcol];
        *(float4*)&Ws[wrow][wcol] = w4;

        __syncthreads();

#pragma unroll
        for (int kk = 0; kk < 16; kk++) {
            float ra[4], rb[4];
#pragma unroll
            for (int i = 0; i < 4; i++) ra[i] = As[kk][ty * 4 + i];
#pragma unroll
            for (int j = 0; j < 4; j++) rb[j] = Ws[kk][tx * 4 + j];
#pragma unroll
            for (int i = 0; i < 4; i++)
#pragma unroll
                for (int j = 0; j < 4; j++)
                    acc[i][j] = fmaf(ra[i], rb[j], acc[i][j]);
        }
        __syncthreads();
    }

    float4 b4 = *(const float4*)&bias[n0 + tx * 4];
#pragma unroll
    for (int i = 0; i < 4; i++) {
        int row = m0 + ty * 4 + i;
        if (row < M) {
            float4 o;
            o.x = acc[i][0] + b4.x;
            o.y = acc[i][1] + b4.y;
            o.z = acc[i][2] + b4.z;
            o.w = acc[i][3] + b4.w;
            *(float4*)&C[(size_t)row * N + n0 + tx * 4] = o;
        }
    }
}

// ---------------------------------------------------------------------------
// Deformable sampling. One warp per (b, q, h); lane = channel (HD=32).
// ---------------------------------------------------------------------------
__global__ __launch_bounds__(256)
void deform_sample(const float* __restrict__ ref,    // [B,L,4,2]
                   const float* __restrict__ offs,   // [B,L,256]
                   const float* __restrict__ logit,  // [B,L,128]
                   const float* __restrict__ val,    // [B,S,NH,HD]
                   float* __restrict__ acc_out) {    // [B,L,NH,HD]
    const int warp = blockIdx.x * 8 + (threadIdx.x >> 5);
    const int lane = threadIdx.x & 31;
    const int total = M_ * NH_;
    if (warp >= total) return;

    const int h  = warp % NH_;
    const int bq = warp / NH_;      // b*L + q
    const int b  = bq / L_;

    // Softmax over 16 logits: lanes 0..15 hold one logit each.
    const float* lg = logit + (size_t)bq * 128 + h * 16;
    float x = (lane < 16) ? lg[lane] : -INFINITY;
    float mx = x;
#pragma unroll
    for (int o = 16; o > 0; o >>= 1)
        mx = fmaxf(mx, __shfl_xor_sync(0xffffffffu, mx, o));
    float e = (lane < 16) ? expf(x - mx) : 0.f;
    float ssum = e;
#pragma unroll
    for (int o = 16; o > 0; o >>= 1)
        ssum += __shfl_xor_sync(0xffffffffu, ssum, o);
    const float wnorm = e / ssum;

    const int   HH[4] = {100, 50, 25, 13};
    const int   ST[4] = {0, 10000, 12500, 13125};

    const float* rp = ref  + (size_t)bq * 8;            // 4 levels x 2
    const float* op = offs + (size_t)bq * 256 + h * 32; // NL*NP*2 per head

    float acc = 0.f;
#pragma unroll
    for (int l = 0; l < 4; l++) {
        const int   Hd = HH[l];
        const int   Wd = HH[l];           // square levels
        const float rx = rp[l * 2 + 0];
        const float ry = rp[l * 2 + 1];
        const float* vbase =
            val + ((size_t)(b * S_ + ST[l]) * NH_ + h) * HD_ + lane;
#pragma unroll
        for (int p = 0; p < 4; p++) {
            const int   s  = l * 4 + p;
            const float ox = op[s * 2 + 0];
            const float oy = op[s * 2 + 1];
            const float xs = rx * (float)Wd + ox - 0.5f;
            const float ys = ry * (float)Hd + oy - 0.5f;
            const float ws = __shfl_sync(0xffffffffu, wnorm, s);

            const int x0 = (int)floorf(xs);
            const int y0 = (int)floorf(ys);
            const float fx = xs - (float)x0;
            const float fy = ys - (float)y0;
            const int x1 = x0 + 1, y1 = y0 + 1;
            const float w00 = (1.f - fx) * (1.f - fy);
            const float w10 = fx * (1.f - fy);
            const float w01 = (1.f - fx) * fy;
            const float w11 = fx * fy;

            float c = 0.f;
            if ((unsigned)x0 < (unsigned)Wd && (unsigned)y0 < (unsigned)Hd)
                c += w00 * vbase[(size_t)(y0 * Wd + x0) * 256];
            if ((unsigned)x1 < (unsigned)Wd && (unsigned)y0 < (unsigned)Hd)
                c += w10 * vbase[(size_t)(y0 * Wd + x1) * 256];
            if ((unsigned)x0 < (unsigned)Wd && (unsigned)y1 < (unsigned)Hd)
                c += w01 * vbase[(size_t)(y1 * Wd + x0) * 256];
            if ((unsigned)x1 < (unsigned)Wd && (unsigned)y1 < (unsigned)Hd)
                c += w11 * vbase[(size_t)(y1 * Wd + x1) * 256];

            acc = fmaf(ws, c, acc);
        }
    }
    acc_out[(size_t)bq * 256 + h * 32 + lane] = acc;
}

// ---------------------------------------------------------------------------
extern "C" void kernel_launch(void* const* d_in, const int* in_sizes, int n_in,
                              void* d_out, int out_size) {
    const float* query  = (const float*)d_in[0];
    const float* refpt  = (const float*)d_in[1];
    const float* value  = (const float*)d_in[2];
    const float* W_val  = (const float*)d_in[3];
    const float* b_val  = (const float*)d_in[4];
    const float* W_off  = (const float*)d_in[5];
    const float* b_off  = (const float*)d_in[6];
    const float* W_attn = (const float*)d_in[7];
    const float* b_attn = (const float*)d_in[8];
    const float* W_out  = (const float*)d_in[9];
    const float* b_out  = (const float*)d_in[10];
    float* out = (float*)d_out;

    float *val_s, *off_s, *lg_s, *acc_s;
    cudaGetSymbolAddress((void**)&val_s, g_val);
    cudaGetSymbolAddress((void**)&off_s, g_off);
    cudaGetSymbolAddress((void**)&lg_s,  g_logit);
    cudaGetSymbolAddress((void**)&acc_s, g_acc);

    const int M = M_;
    dim3 blk(256);
    dim3 gN256(256 / 64, (M + 63) / 64);
    dim3 gN128(128 / 64, (M + 63) / 64);

    // Projections
    sgemm_bias<<<gN256, blk>>>(value, W_val, b_val, val_s, M, 256, 256);
    sgemm_bias<<<gN256, blk>>>(query, W_off, b_off, off_s, M, 256, 256);
    sgemm_bias<<<gN128, blk>>>(query, W_attn, b_attn, lg_s, M, 128, 256);

    // Deformable sampling: one warp per (b,q,h)
    const int warps = M * NH_;
    deform_sample<<<(warps + 7) / 8, 256>>>(refpt, off_s, lg_s, val_s, acc_s);

    // Output projection -> d_out
    sgemm_bias<<<gN256, blk>>>(acc_s, W_out, b_out, out, M, 256, 256);
}